// round 16
// baseline (speedup 1.0000x reference)
#include <cuda_runtime.h>
#include <math.h>

#define DIM 512
#define NF4 (DIM / 4)
#define TAU 0.1f
#define EPS_NORM 1e-12f
#define EPS_DENOM 1e-8f
#define MAX_POS 32768

__device__ double g_neg_sum = 0.0;
__device__ double g_pos_sum = 0.0;
__device__ float  g_pos_eml[MAX_POS];   // exp(-logit) per positive

__device__ __forceinline__ float block_reduce_sum(float v, float* part, int warps) {
    const int lane = threadIdx.x & 31;
    const int warp = threadIdx.x >> 5;
    #pragma unroll
    for (int o = 16; o > 0; o >>= 1) v += __shfl_xor_sync(0xffffffffu, v, o);
    if (lane == 0) part[warp] = v;
    __syncthreads();
    float r = 0.0f;
    for (int i = 0; i < warps; i++) r += part[i];
    __syncthreads();
    return r;
}

// ---------------------------------------------------------------------------
// k_main: grid = [mix blocks | neg blocks | pos blocks], 256 threads, 1 row
// per warp. R12 body with DEFAULT-policy streaming loads (no .cs hint) and
// pos path storing exp(-l).
// ---------------------------------------------------------------------------
template<int WARPS>
__global__ void __launch_bounds__(WARPS * 32) k_main(
    const float4* __restrict__ h,
    const float4* __restrict__ p,
    const float4* __restrict__ anchor4,
    const int*    __restrict__ mix_idx,
    const int*    __restrict__ idx_a,
    const int*    __restrict__ idx_b,
    const float*  __restrict__ alpha_raw,
    const float*  __restrict__ beta_raw,
    int nb_neg, int nb_pos,
    int n_hard, int n_pos, int n_mix)
{
    __shared__ float4 sav[NF4];     // RAW anchor (2 KB)
    __shared__ float  part[WARPS];

    const int tid  = threadIdx.x;
    const int warp = tid >> 5;
    const int lane = tid & 31;
    const int b    = blockIdx.x;
    const int nmix2 = 2 * n_mix;

    // stage anchor into shared (no barrier yet)
    if (tid < NF4) sav[tid] = __ldg(&anchor4[tid]);

    if (b >= nmix2) {
        // ----- streaming path: one row per warp -----
        const int     sb     = b - nmix2;
        const bool    is_neg = (sb < nb_neg);
        const int     bb     = is_neg ? sb : sb - nb_neg;
        const int     nrows  = is_neg ? n_hard : n_pos;
        const float4* base   = is_neg ? h : p;
        const int     row    = bb * WARPS + warp;
        const bool    valid  = (row < nrows);

        // issue the 4 streaming loads BEFORE the barrier — latency hides it.
        // Default cache policy (L2-promoting LDG), not evict-first.
        float4 v0, v1, v2, v3;
        if (valid) {
            const float4* r = base + (size_t)row * NF4 + lane;
            v0 = r[ 0];
            v1 = r[32];
            v2 = r[64];
            v3 = r[96];
        } else {
            v0 = v1 = v2 = v3 = make_float4(0.f, 0.f, 0.f, 0.f);
        }

        __syncthreads();   // sav visible (single barrier before compute)

        float4 a0 = sav[lane +  0];
        float4 a1 = sav[lane + 32];
        float4 a2 = sav[lane + 64];
        float4 a3 = sav[lane + 96];

        // per-warp ||a||^2 (overlaps with v-load latency)
        float sa = a0.x*a0.x + a0.y*a0.y + a0.z*a0.z + a0.w*a0.w
                 + a1.x*a1.x + a1.y*a1.y + a1.z*a1.z + a1.w*a1.w
                 + a2.x*a2.x + a2.y*a2.y + a2.z*a2.z + a2.w*a2.w
                 + a3.x*a3.x + a3.y*a3.y + a3.z*a3.z + a3.w*a3.w;
        #pragma unroll
        for (int o = 16; o > 0; o >>= 1) sa += __shfl_xor_sync(0xffffffffu, sa, o);

        float d  = v0.x*a0.x + v0.y*a0.y + v0.z*a0.z + v0.w*a0.w
                 + v1.x*a1.x + v1.y*a1.y + v1.z*a1.z + v1.w*a1.w
                 + v2.x*a2.x + v2.y*a2.y + v2.z*a2.z + v2.w*a2.w
                 + v3.x*a3.x + v3.y*a3.y + v3.z*a3.z + v3.w*a3.w;
        float sv = v0.x*v0.x + v0.y*v0.y + v0.z*v0.z + v0.w*v0.w
                 + v1.x*v1.x + v1.y*v1.y + v1.z*v1.z + v1.w*v1.w
                 + v2.x*v2.x + v2.y*v2.y + v2.z*v2.z + v2.w*v2.w
                 + v3.x*v3.x + v3.y*v3.y + v3.z*v3.z + v3.w*v3.w;
        #pragma unroll
        for (int o = 16; o > 0; o >>= 1) {
            d  += __shfl_xor_sync(0xffffffffu, d, o);
            sv += __shfl_xor_sync(0xffffffffu, sv, o);
        }

        if (is_neg) {
            float ex = 0.0f;
            if (lane == 0 && valid) {
                float l = d / (fmaxf(sqrtf(sa), EPS_NORM) *
                               fmaxf(sqrtf(sv), EPS_NORM) * TAU);
                ex = expf(l);
            }
            if (lane == 0) part[warp] = ex;
            __syncthreads();
            if (tid == 0) {
                float s = 0.0f;
                #pragma unroll
                for (int i = 0; i < WARPS; i++) s += part[i];
                atomicAdd(&g_neg_sum, (double)s);   // one f64 atomic per block
            }
        } else if (lane == 0 && valid) {
            float l = d / (fmaxf(sqrtf(sa), EPS_NORM) *
                           fmaxf(sqrtf(sv), EPS_NORM) * TAU);
            g_pos_eml[row] = expf(-l);              // store exp(-l)
        }
        return;
    }

    // ----- mix path: one synthesized negative per block (scheduled first) ----
    __syncthreads();   // sav visible
    const int j  = b;                              // 0 .. 2*n_mix-1
    const float* hs = (const float*)h;

    const bool active = (tid < NF4);
    float4 araw = active ? sav[tid] : make_float4(0.f, 0.f, 0.f, 0.f);
    float ssa = block_reduce_sum(
        araw.x*araw.x + araw.y*araw.y + araw.z*araw.z + araw.w*araw.w,
        part, WARPS);
    float inv_na = 1.0f / fmaxf(sqrtf(ssa), EPS_NORM);
    float4 a = make_float4(araw.x * inv_na, araw.y * inv_na,
                           araw.z * inv_na, araw.w * inv_na);

    float4 v = make_float4(0.f, 0.f, 0.f, 0.f);

    if (j < n_mix) {
        // hardest = l2norm((1-alpha) * h_norm[m] + alpha * a_norm)
        int   m     = mix_idx[j];
        float alpha = alpha_raw[j] * 0.4f + 0.1f;
        float4 x = make_float4(0.f, 0.f, 0.f, 0.f);
        if (active) x = ((const float4*)(hs + (size_t)m * DIM))[tid];
        float ssx = block_reduce_sum(
            x.x*x.x + x.y*x.y + x.z*x.z + x.w*x.w, part, WARPS);
        float inv = (1.0f - alpha) / fmaxf(sqrtf(ssx), EPS_NORM);
        v.x = x.x * inv + alpha * a.x;
        v.y = x.y * inv + alpha * a.y;
        v.z = x.z * inv + alpha * a.z;
        v.w = x.w * inv + alpha * a.w;
    } else {
        // harder = l2norm(beta * h_norm[ia] + (1-beta) * h_norm[ib])
        int   jj   = j - n_mix;
        int   ia   = idx_a[jj];
        int   ib   = idx_b[jj];
        float beta = beta_raw[jj] * 0.4f + 0.3f;
        float4 xa = make_float4(0.f, 0.f, 0.f, 0.f);
        float4 xb = make_float4(0.f, 0.f, 0.f, 0.f);
        if (active) {
            xa = ((const float4*)(hs + (size_t)ia * DIM))[tid];
            xb = ((const float4*)(hs + (size_t)ib * DIM))[tid];
        }
        float ssaa = block_reduce_sum(
            xa.x*xa.x + xa.y*xa.y + xa.z*xa.z + xa.w*xa.w, part, WARPS);
        float ssbb = block_reduce_sum(
            xb.x*xb.x + xb.y*xb.y + xb.z*xb.z + xb.w*xb.w, part, WARPS);
        float inva = beta          / fmaxf(sqrtf(ssaa), EPS_NORM);
        float invb = (1.0f - beta) / fmaxf(sqrtf(ssbb), EPS_NORM);
        v.x = xa.x * inva + xb.x * invb;
        v.y = xa.y * inva + xb.y * invb;
        v.z = xa.z * inva + xb.z * invb;
        v.w = xa.w * inva + xb.w * invb;
    }

    float ssv = block_reduce_sum(
        v.x*v.x + v.y*v.y + v.z*v.z + v.w*v.w, part, WARPS);
    float dv = block_reduce_sum(
        v.x*a.x + v.y*a.y + v.z*a.z + v.w*a.w, part, WARPS);

    if (tid == 0) {
        float l = dv / (fmaxf(sqrtf(ssv), EPS_NORM) * TAU);
        atomicAdd(&g_neg_sum, (double)expf(l));
    }
}

// ---------------------------------------------------------------------------
// k_pos_reduce: 32 blocks, one element per thread: log1p(S * eml[i]).
// Block partial (double) -> one atomicAdd per block. No fences, no tickets.
// ---------------------------------------------------------------------------
__global__ void __launch_bounds__(256) k_pos_reduce(int n_pos) {
    __shared__ double red[8];
    __shared__ float  sh_S;
    const int tid = threadIdx.x;
    const int i   = blockIdx.x * 256 + tid;

    if (tid == 0) sh_S = (float)g_neg_sum + EPS_DENOM;
    __syncthreads();
    const float S = sh_S;

    double acc = 0.0;
    if (i < n_pos) {
        acc = (double)log1pf(S * g_pos_eml[i]);
    }
    #pragma unroll
    for (int o = 16; o > 0; o >>= 1)
        acc += __shfl_xor_sync(0xffffffffu, acc, o);
    if ((tid & 31) == 0) red[tid >> 5] = acc;
    __syncthreads();
    if (tid == 0) {
        double s = 0.0;
        #pragma unroll
        for (int k = 0; k < 8; k++) s += red[k];
        atomicAdd(&g_pos_sum, s);
    }
}

// ---------------------------------------------------------------------------
// k_write: one thread. Writes loss; resets accumulators for next replay.
// ---------------------------------------------------------------------------
__global__ void k_write(float* __restrict__ out, double inv_npos) {
    out[0] = (float)(g_pos_sum * inv_npos);
    g_pos_sum = 0.0;
    g_neg_sum = 0.0;
}

extern "C" void kernel_launch(void* const* d_in, const int* in_sizes, int n_in,
                              void* d_out, int out_size) {
    const float* anchor    = (const float*)d_in[0];
    const float* positives = (const float*)d_in[1];
    const float* hardnegs  = (const float*)d_in[2];
    const int*   mix_idx   = (const int*)d_in[3];
    const int*   idx_a     = (const int*)d_in[4];
    const int*   idx_b     = (const int*)d_in[5];
    const float* alpha_raw = (const float*)d_in[6];
    const float* beta_raw  = (const float*)d_in[7];

    const int n_pos  = in_sizes[1] / DIM;
    const int n_hard = in_sizes[2] / DIM;
    const int n_mix  = in_sizes[3];

    constexpr int WARPS = 8;
    const int nb_neg = (n_hard + WARPS - 1) / WARPS;
    const int nb_pos = (n_pos  + WARPS - 1) / WARPS;
    const int grid   = 2 * n_mix + nb_neg + nb_pos;

    k_main<WARPS><<<grid, WARPS * 32>>>(
        (const float4*)hardnegs, (const float4*)positives,
        (const float4*)anchor,
        mix_idx, idx_a, idx_b, alpha_raw, beta_raw,
        nb_neg, nb_pos, n_hard, n_pos, n_mix);

    k_pos_reduce<<<(n_pos + 255) / 256, 256>>>(n_pos);
    k_write<<<1, 1>>>((float*)d_out, 1.0 / (double)n_pos);
}

// round 17
// speedup vs baseline: 1.1979x; 1.1979x over previous
#include <cuda_runtime.h>
#include <math.h>

#define DIM 512
#define NF4 (DIM / 4)
#define TAU 0.1f
#define EPS_NORM 1e-12f
#define EPS_DENOM 1e-8f
#define MAX_POS 32768

__device__ double g_neg_sum = 0.0;
__device__ double g_pos_sum = 0.0;
__device__ float  g_pos_logit[MAX_POS];

__device__ __forceinline__ float block_reduce_sum(float v, float* part, int warps) {
    const int lane = threadIdx.x & 31;
    const int warp = threadIdx.x >> 5;
    #pragma unroll
    for (int o = 16; o > 0; o >>= 1) v += __shfl_xor_sync(0xffffffffu, v, o);
    if (lane == 0) part[warp] = v;
    __syncthreads();
    float r = 0.0f;
    for (int i = 0; i < warps; i++) r += part[i];
    __syncthreads();
    return r;
}

// ---------------------------------------------------------------------------
// k_main: grid = [mix blocks | neg blocks | pos blocks], 256 threads, 1 row
// per warp (session optimum). __ldcs evict-first streaming loads (confirmed
// +20% DRAM vs default in R16 A/B). Single barrier hidden behind row loads.
// One f64 atomic per neg block.
// ---------------------------------------------------------------------------
template<int WARPS>
__global__ void __launch_bounds__(WARPS * 32) k_main(
    const float4* __restrict__ h,
    const float4* __restrict__ p,
    const float4* __restrict__ anchor4,
    const int*    __restrict__ mix_idx,
    const int*    __restrict__ idx_a,
    const int*    __restrict__ idx_b,
    const float*  __restrict__ alpha_raw,
    const float*  __restrict__ beta_raw,
    int nb_neg, int nb_pos,
    int n_hard, int n_pos, int n_mix)
{
    __shared__ float4 sav[NF4];     // RAW anchor (2 KB)
    __shared__ float  part[WARPS];

    const int tid  = threadIdx.x;
    const int warp = tid >> 5;
    const int lane = tid & 31;
    const int b    = blockIdx.x;
    const int nmix2 = 2 * n_mix;

    // stage anchor into shared (no barrier yet)
    if (tid < NF4) sav[tid] = __ldg(&anchor4[tid]);

    if (b >= nmix2) {
        // ----- streaming path: one row per warp -----
        const int     sb     = b - nmix2;
        const bool    is_neg = (sb < nb_neg);
        const int     bb     = is_neg ? sb : sb - nb_neg;
        const int     nrows  = is_neg ? n_hard : n_pos;
        const float4* base   = is_neg ? h : p;
        const int     row    = bb * WARPS + warp;
        const bool    valid  = (row < nrows);

        // issue the 4 streaming loads BEFORE the barrier — latency hides it
        float4 v0, v1, v2, v3;
        if (valid) {
            const float4* r = base + (size_t)row * NF4 + lane;
            v0 = __ldcs(r +  0);
            v1 = __ldcs(r + 32);
            v2 = __ldcs(r + 64);
            v3 = __ldcs(r + 96);
        } else {
            v0 = v1 = v2 = v3 = make_float4(0.f, 0.f, 0.f, 0.f);
        }

        __syncthreads();   // sav visible (single barrier before compute)

        float4 a0 = sav[lane +  0];
        float4 a1 = sav[lane + 32];
        float4 a2 = sav[lane + 64];
        float4 a3 = sav[lane + 96];

        // per-warp ||a||^2 (overlaps with v-load latency)
        float sa = a0.x*a0.x + a0.y*a0.y + a0.z*a0.z + a0.w*a0.w
                 + a1.x*a1.x + a1.y*a1.y + a1.z*a1.z + a1.w*a1.w
                 + a2.x*a2.x + a2.y*a2.y + a2.z*a2.z + a2.w*a2.w
                 + a3.x*a3.x + a3.y*a3.y + a3.z*a3.z + a3.w*a3.w;
        #pragma unroll
        for (int o = 16; o > 0; o >>= 1) sa += __shfl_xor_sync(0xffffffffu, sa, o);

        float d  = v0.x*a0.x + v0.y*a0.y + v0.z*a0.z + v0.w*a0.w
                 + v1.x*a1.x + v1.y*a1.y + v1.z*a1.z + v1.w*a1.w
                 + v2.x*a2.x + v2.y*a2.y + v2.z*a2.z + v2.w*a2.w
                 + v3.x*a3.x + v3.y*a3.y + v3.z*a3.z + v3.w*a3.w;
        float sv = v0.x*v0.x + v0.y*v0.y + v0.z*v0.z + v0.w*v0.w
                 + v1.x*v1.x + v1.y*v1.y + v1.z*v1.z + v1.w*v1.w
                 + v2.x*v2.x + v2.y*v2.y + v2.z*v2.z + v2.w*v2.w
                 + v3.x*v3.x + v3.y*v3.y + v3.z*v3.z + v3.w*v3.w;
        #pragma unroll
        for (int o = 16; o > 0; o >>= 1) {
            d  += __shfl_xor_sync(0xffffffffu, d, o);
            sv += __shfl_xor_sync(0xffffffffu, sv, o);
        }

        if (is_neg) {
            float ex = 0.0f;
            if (lane == 0 && valid) {
                float l = d / (fmaxf(sqrtf(sa), EPS_NORM) *
                               fmaxf(sqrtf(sv), EPS_NORM) * TAU);
                ex = expf(l);
            }
            if (lane == 0) part[warp] = ex;
            __syncthreads();
            if (tid == 0) {
                float s = 0.0f;
                #pragma unroll
                for (int i = 0; i < WARPS; i++) s += part[i];
                atomicAdd(&g_neg_sum, (double)s);   // one f64 atomic per block
            }
        } else if (lane == 0 && valid) {
            float l = d / (fmaxf(sqrtf(sa), EPS_NORM) *
                           fmaxf(sqrtf(sv), EPS_NORM) * TAU);
            g_pos_logit[row] = l;
        }
        return;
    }

    // ----- mix path: one synthesized negative per block (scheduled first) ----
    __syncthreads();   // sav visible
    const int j  = b;                              // 0 .. 2*n_mix-1
    const float* hs = (const float*)h;

    const bool active = (tid < NF4);
    float4 araw = active ? sav[tid] : make_float4(0.f, 0.f, 0.f, 0.f);
    float ssa = block_reduce_sum(
        araw.x*araw.x + araw.y*araw.y + araw.z*araw.z + araw.w*araw.w,
        part, WARPS);
    float inv_na = 1.0f / fmaxf(sqrtf(ssa), EPS_NORM);
    float4 a = make_float4(araw.x * inv_na, araw.y * inv_na,
                           araw.z * inv_na, araw.w * inv_na);

    float4 v = make_float4(0.f, 0.f, 0.f, 0.f);

    if (j < n_mix) {
        // hardest = l2norm((1-alpha) * h_norm[m] + alpha * a_norm)
        int   m     = mix_idx[j];
        float alpha = alpha_raw[j] * 0.4f + 0.1f;
        float4 x = make_float4(0.f, 0.f, 0.f, 0.f);
        if (active) x = ((const float4*)(hs + (size_t)m * DIM))[tid];
        float ssx = block_reduce_sum(
            x.x*x.x + x.y*x.y + x.z*x.z + x.w*x.w, part, WARPS);
        float inv = (1.0f - alpha) / fmaxf(sqrtf(ssx), EPS_NORM);
        v.x = x.x * inv + alpha * a.x;
        v.y = x.y * inv + alpha * a.y;
        v.z = x.z * inv + alpha * a.z;
        v.w = x.w * inv + alpha * a.w;
    } else {
        // harder = l2norm(beta * h_norm[ia] + (1-beta) * h_norm[ib])
        int   jj   = j - n_mix;
        int   ia   = idx_a[jj];
        int   ib   = idx_b[jj];
        float beta = beta_raw[jj] * 0.4f + 0.3f;
        float4 xa = make_float4(0.f, 0.f, 0.f, 0.f);
        float4 xb = make_float4(0.f, 0.f, 0.f, 0.f);
        if (active) {
            xa = ((const float4*)(hs + (size_t)ia * DIM))[tid];
            xb = ((const float4*)(hs + (size_t)ib * DIM))[tid];
        }
        float ssaa = block_reduce_sum(
            xa.x*xa.x + xa.y*xa.y + xa.z*xa.z + xa.w*xa.w, part, WARPS);
        float ssbb = block_reduce_sum(
            xb.x*xb.x + xb.y*xb.y + xb.z*xb.z + xb.w*xb.w, part, WARPS);
        float inva = beta          / fmaxf(sqrtf(ssaa), EPS_NORM);
        float invb = (1.0f - beta) / fmaxf(sqrtf(ssbb), EPS_NORM);
        v.x = xa.x * inva + xb.x * invb;
        v.y = xa.y * inva + xb.y * invb;
        v.z = xa.z * inva + xb.z * invb;
        v.w = xa.w * inva + xb.w * invb;
    }

    float ssv = block_reduce_sum(
        v.x*v.x + v.y*v.y + v.z*v.z + v.w*v.w, part, WARPS);
    float dv = block_reduce_sum(
        v.x*a.x + v.y*a.y + v.z*a.z + v.w*a.w, part, WARPS);

    if (tid == 0) {
        float l = dv / (fmaxf(sqrtf(ssv), EPS_NORM) * TAU);
        atomicAdd(&g_neg_sum, (double)expf(l));
    }
}

// ---------------------------------------------------------------------------
// k_pos_reduce: 32 blocks, one logit per thread. Block partial (double) ->
// one atomicAdd per block into g_pos_sum. No fences, no tickets.
// ---------------------------------------------------------------------------
__global__ void __launch_bounds__(256) k_pos_reduce(int n_pos) {
    __shared__ double red[8];
    __shared__ float  sh_S;
    const int tid = threadIdx.x;
    const int i   = blockIdx.x * 256 + tid;

    if (tid == 0) sh_S = (float)g_neg_sum + EPS_DENOM;
    __syncthreads();
    const float S = sh_S;

    double acc = 0.0;
    if (i < n_pos) {
        float l = g_pos_logit[i];
        acc = (double)log1pf(S * expf(-l));
    }
    #pragma unroll
    for (int o = 16; o > 0; o >>= 1)
        acc += __shfl_xor_sync(0xffffffffu, acc, o);
    if ((tid & 31) == 0) red[tid >> 5] = acc;
    __syncthreads();
    if (tid == 0) {
        double s = 0.0;
        #pragma unroll
        for (int k = 0; k < 8; k++) s += red[k];
        atomicAdd(&g_pos_sum, s);
    }
}

// ---------------------------------------------------------------------------
// k_write: one thread. Writes loss; resets accumulators for next replay.
// ---------------------------------------------------------------------------
__global__ void k_write(float* __restrict__ out, double inv_npos) {
    out[0] = (float)(g_pos_sum * inv_npos);
    g_pos_sum = 0.0;
    g_neg_sum = 0.0;
}

extern "C" void kernel_launch(void* const* d_in, const int* in_sizes, int n_in,
                              void* d_out, int out_size) {
    const float* anchor    = (const float*)d_in[0];
    const float* positives = (const float*)d_in[1];
    const float* hardnegs  = (const float*)d_in[2];
    const int*   mix_idx   = (const int*)d_in[3];
    const int*   idx_a     = (const int*)d_in[4];
    const int*   idx_b     = (const int*)d_in[5];
    const float* alpha_raw = (const float*)d_in[6];
    const float* beta_raw  = (const float*)d_in[7];

    const int n_pos  = in_sizes[1] / DIM;
    const int n_hard = in_sizes[2] / DIM;
    const int n_mix  = in_sizes[3];

    constexpr int WARPS = 8;
    const int nb_neg = (n_hard + WARPS - 1) / WARPS;
    const int nb_pos = (n_pos  + WARPS - 1) / WARPS;
    const int grid   = 2 * n_mix + nb_neg + nb_pos;

    k_main<WARPS><<<grid, WARPS * 32>>>(
        (const float4*)hardnegs, (const float4*)positives,
        (const float4*)anchor,
        mix_idx, idx_a, idx_b, alpha_raw, beta_raw,
        nb_neg, nb_pos, n_hard, n_pos, n_mix);

    k_pos_reduce<<<(n_pos + 255) / 256, 256>>>(n_pos);
    k_write<<<1, 1>>>((float*)d_out, 1.0 / (double)n_pos);
}